// round 3
// baseline (speedup 1.0000x reference)
#include <cuda_runtime.h>

// Grid: 128^3 cells, cell = (bin+64), idx = x + 128*y + 16384*z
// Each cell: float4 {sum_x, sum_y, sum_z, count}
#define D    128
#define D3   (128*128*128)
#define OFF  64
#define NMAX 200704

__device__ float4 g_grid0[D3];     // scatter target (zeroed back by gather)
__device__ float4 g_grid1[D3];     // conv output / gather source
__device__ float  g_Xbuf[2][NMAX * 3];
__device__ int    g_actYZ[16 * 128];  // activity flag per (ytile=y>>3, z)
__device__ unsigned g_maxd2_bits;
__device__ int g_done;

// ---------------------------------------------------------------- helpers
__device__ __forceinline__ int bin_of(float v) {
    // match jnp: (X / 0.1f).astype(int32) == IEEE RN divide, trunc toward zero
    int b = (int)__fdiv_rn(v, 0.1f);
    b += OFF;
    return min(max(b, 0), D - 1);
}

__device__ __forceinline__ void fma4(float4& a, float w, const float4 v) {
    a.x += w * v.x; a.y += w * v.y; a.z += w * v.z; a.w += w * v.w;
}

// ---------------------------------------------------------------- scatter
// Warp-aggregated: group lanes by cell, shuffle-sum, one red.v4 per group.
__global__ void scatter_kernel(const float* __restrict__ Xext, int srcSel, int n, int first) {
    if (blockIdx.x == 0 && threadIdx.x == 0) {
        // fold convergence check: uses previous step's max displacement^2
        if (first) g_done = 0;
        else if (__uint_as_float(g_maxd2_bits) <= 1e-6f) g_done = 1;
        g_maxd2_bits = 0u;
    }
    const float* X = (srcSel < 0) ? Xext : g_Xbuf[srcSel];
    int i = blockIdx.x * blockDim.x + threadIdx.x;
    unsigned active = __ballot_sync(0xffffffffu, i < n);
    if (i >= n) return;
    float x = X[3 * i + 0];
    float y = X[3 * i + 1];
    float z = X[3 * i + 2];
    int yb = bin_of(y), zb = bin_of(z);
    int cell = bin_of(x) + (yb << 7) + (zb << 14);

    unsigned grp = __match_any_sync(active, cell);
    int lane = threadIdx.x & 31;
    float sx = 0.f, sy = 0.f, sz = 0.f;
    unsigned m = grp;
    do {
        int src = __ffs(m) - 1;
        sx += __shfl_sync(grp, x, src);
        sy += __shfl_sync(grp, y, src);
        sz += __shfl_sync(grp, z, src);
        m &= m - 1;
    } while (m);

    if (lane == __ffs(grp) - 1) {
        g_actYZ[((yb >> 3) << 7) + zb] = 1;
        float sw = (float)__popc(grp);
        asm volatile("red.global.add.v4.f32 [%0], {%1, %2, %3, %4};"
                     :: "l"(&g_grid0[cell]), "f"(sx), "f"(sy), "f"(sz), "f"(sw)
                     : "memory");
    }
}

// ---------------------------------------------------------------- fused 3D separable conv
// weights [1,2,3,2,1] per axis. Block: x full line (128) x 8 y-rows, z-seg of 8.
// 256 blocks x 1024 threads. Window trimmed by activity flags.

__device__ __forceinline__ void load_slice(int zc, int x, int r, int y0,
                                           float4& a, float4& b) {
    int zoff = (min(max(zc, 0), D - 1)) << 14;
    int ya = min(max(y0 + r - 2, 0), D - 1);
    a = g_grid0[x + (ya << 7) + zoff];
    if (r < 4) {
        int yb = min(max(y0 + r + 6, 0), D - 1);
        b = g_grid0[x + (yb << 7) + zoff];
    }
}

__global__ __launch_bounds__(1024) void conv3d_kernel() {
    __shared__ float4 raw[12][D];
    __shared__ float4 xf[12][D];
    __shared__ unsigned s_mask;

    int x = threadIdx.x & 127;
    int r = threadIdx.x >> 7;            // 0..7
    int yt = blockIdx.x & 15;            // 16 y-tiles of 8 rows
    int zseg = blockIdx.x >> 4;          // 16 z-segments of 8 slices
    int y0 = yt << 3;
    int z0 = zseg << 3;

    // which output slices in this segment are needed?
    if (threadIdx.x < 32) {
        int f = (threadIdx.x < 8) ? g_actYZ[(yt << 7) + z0 + threadIdx.x] : 0;
        unsigned bm = __ballot_sync(0xffffffffu, f != 0);
        if (threadIdx.x == 0) s_mask = bm;
    }
    __syncthreads();
    unsigned need = s_mask;
    if (!need) return;
    int zlo = z0 + __ffs(need) - 1;
    int zhi = z0 + 31 - __clz(need);
    int nslices = zhi - zlo + 5;         // raw slices zlo-2 .. zhi+2

    const float W0 = 1.f, W1 = 2.f, W2 = 3.f, W3 = 2.f, W4 = 1.f;

    float4 r0, r1, r2, r3, r4;           // z ring
    r0 = r1 = r2 = r3 = r4 = make_float4(0.f, 0.f, 0.f, 0.f);

    float4 pa, pb;                       // prefetch regs
    load_slice(zlo - 2, x, r, y0, pa, pb);

#pragma unroll 1
    for (int zi = 0; zi < nslices; zi++) {
        int zc = zlo - 2 + zi;
        raw[r][x] = pa;
        if (r < 4) raw[r + 8][x] = pb;
        __syncthreads();

        if (zi < nslices - 1) load_slice(zc + 1, x, r, y0, pa, pb);

        // x-filter
        {
            int xm2 = max(x - 2, 0), xm1 = max(x - 1, 0);
            int xp1 = min(x + 1, D - 1), xp2 = min(x + 2, D - 1);
            float4 a = make_float4(0.f, 0.f, 0.f, 0.f);
            fma4(a, W0, raw[r][xm2]); fma4(a, W1, raw[r][xm1]);
            fma4(a, W2, raw[r][x]);   fma4(a, W3, raw[r][xp1]);
            fma4(a, W4, raw[r][xp2]);
            xf[r][x] = a;
            if (r < 4) {
                float4 b = make_float4(0.f, 0.f, 0.f, 0.f);
                fma4(b, W0, raw[r + 8][xm2]); fma4(b, W1, raw[r + 8][xm1]);
                fma4(b, W2, raw[r + 8][x]);   fma4(b, W3, raw[r + 8][xp1]);
                fma4(b, W4, raw[r + 8][xp2]);
                xf[r + 8][x] = b;
            }
        }
        __syncthreads();

        // y-filter for core row (global y = y0 + r)
        float4 a = make_float4(0.f, 0.f, 0.f, 0.f);
        fma4(a, W0, xf[r + 0][x]);
        fma4(a, W1, xf[r + 1][x]);
        fma4(a, W2, xf[r + 2][x]);
        fma4(a, W3, xf[r + 3][x]);
        fma4(a, W4, xf[r + 4][x]);

        r0 = r1; r1 = r2; r2 = r3; r3 = r4; r4 = a;

        if (zi >= 4) {
            int zo = zc - 2;             // zlo .. zhi
            float4 o;
            o.x = r0.x + 2.f * r1.x + 3.f * r2.x + 2.f * r3.x + r4.x;
            o.y = r0.y + 2.f * r1.y + 3.f * r2.y + 2.f * r3.y + r4.y;
            o.z = r0.z + 2.f * r1.z + 3.f * r2.z + 2.f * r3.z + r4.z;
            o.w = r0.w + 2.f * r1.w + 3.f * r2.w + 2.f * r3.w + r4.w;
            g_grid1[x + ((y0 + r) << 7) + (zo << 14)] = o;
        }
        // no third sync: next raw store races only with xf reads (disjoint arrays)
    }
}

// ---------------------------------------------------------------- gather (+ zero grid0 + clear flags)
__global__ void gather_kernel(const float* __restrict__ Xext, int srcSel,
                              float* __restrict__ Oext, int dstSel, int n) {
    __shared__ float s_max[8];
    const float* X = (srcSel < 0) ? Xext : g_Xbuf[srcSel];
    float* Y = (dstSel < 0) ? Oext : g_Xbuf[dstSel];
    int i = blockIdx.x * blockDim.x + threadIdx.x;
    float d2 = 0.f;
    if (i < n) {
        float x = X[3 * i + 0];
        float y = X[3 * i + 1];
        float z = X[3 * i + 2];
        int yb = bin_of(y), zb = bin_of(z);
        int cell = bin_of(x) + (yb << 7) + (zb << 14);
        float4 t = g_grid1[cell];
        // undo this step's scatter: keeps grid0 & flags all-zero at step/replay boundaries
        g_grid0[cell] = make_float4(0.f, 0.f, 0.f, 0.f);
        g_actYZ[((yb >> 3) << 7) + zb] = 0;
        float nx = __fdiv_rn(t.x, t.w);
        float ny = __fdiv_rn(t.y, t.w);
        float nz = __fdiv_rn(t.z, t.w);
        if (g_done) { nx = x; ny = y; nz = z; }
        Y[3 * i + 0] = nx;
        Y[3 * i + 1] = ny;
        Y[3 * i + 2] = nz;
        float dx = nx - x, dy = ny - y, dz = nz - z;
        d2 = dx * dx + dy * dy + dz * dz;
    }
#pragma unroll
    for (int o = 16; o > 0; o >>= 1)
        d2 = fmaxf(d2, __shfl_xor_sync(0xFFFFFFFFu, d2, o));
    int wid = threadIdx.x >> 5;
    if ((threadIdx.x & 31) == 0) s_max[wid] = d2;
    __syncthreads();
    if (threadIdx.x < 8) {
        float v = s_max[threadIdx.x];
#pragma unroll
        for (int o = 4; o > 0; o >>= 1)
            v = fmaxf(v, __shfl_xor_sync(0xFFu, v, o));
        if (threadIdx.x == 0)
            atomicMax(&g_maxd2_bits, __float_as_uint(v));
    }
}

// ---------------------------------------------------------------- launch
extern "C" void kernel_launch(void* const* d_in, const int* in_sizes, int n_in,
                              void* d_out, int out_size) {
    const float* Xin = (const float*)d_in[0];
    float* Out = (float*)d_out;
    int n = in_sizes[0] / 3;

    int pblocks = (n + 255) / 256;
    int srcSel[5] = {-1, 0, 1, 0, 1};
    int dstSel[5] = { 0, 1, 0, 1, -1};

    for (int s = 0; s < 5; s++) {
        scatter_kernel<<<pblocks, 256>>>(Xin, srcSel[s], n, s == 0);
        conv3d_kernel<<<256, 1024>>>();
        gather_kernel<<<pblocks, 256>>>(Xin, srcSel[s], Out, dstSel[s], n);
    }
}

// round 4
// speedup vs baseline: 1.1132x; 1.1132x over previous
#include <cuda_runtime.h>

// Grid: 128^3 cells, cell = (bin+64), idx = x + 128*y + 16384*z
// Each cell: float4 {sum_x, sum_y, sum_z, count}
#define D    128
#define D3   (128*128*128)
#define OFF  64
#define NMAX 200704

__device__ float4 g_gridA[D3];     // scatter ping
__device__ float4 g_gridB[D3];     // scatter pong
__device__ float4 g_grid1[D3];     // conv output / gather source
__device__ float  g_Xbuf[2][NMAX * 3];
__device__ int    g_actA[16 * 128];   // activity flag per (ytile=y>>3, z)
__device__ int    g_actB[16 * 128];
__device__ unsigned g_maxd2_bits;
__device__ int g_done;

// ---------------------------------------------------------------- helpers
__device__ __forceinline__ int bin_of(float v) {
    // match jnp: (X / 0.1f).astype(int32) == IEEE RN divide, trunc toward zero
    int b = (int)__fdiv_rn(v, 0.1f);
    b += OFF;
    return min(max(b, 0), D - 1);
}

__device__ __forceinline__ void fma4(float4& a, float w, const float4 v) {
    a.x += w * v.x; a.y += w * v.y; a.z += w * v.z; a.w += w * v.w;
}

__device__ __forceinline__ void red4(float4* p, float x, float y, float z, float w) {
    asm volatile("red.global.add.v4.f32 [%0], {%1, %2, %3, %4};"
                 :: "l"(p), "f"(x), "f"(y), "f"(z), "f"(w) : "memory");
}

// ---------------------------------------------------------------- initial scatter (step 0 only)
__global__ void scatter0_kernel(const float* __restrict__ X, int n) {
    int i = blockIdx.x * blockDim.x + threadIdx.x;
    if (i >= n) return;
    float x = X[3 * i + 0];
    float y = X[3 * i + 1];
    float z = X[3 * i + 2];
    int yb = bin_of(y), zb = bin_of(z);
    int cell = bin_of(x) + (yb << 7) + (zb << 14);
    g_actA[((yb >> 3) << 7) + zb] = 1;
    red4(&g_gridA[cell], x, y, z, 1.0f);
}

// ---------------------------------------------------------------- fused 3D separable conv
// weights [1,2,3,2,1] per axis. Block: full x-line (128) x 8 y-rows, z-seg of 8.
// 256 blocks x 1024 threads. Window trimmed by activity flags.
// Also folds the convergence bookkeeping (block 0, thread 0).

__device__ __forceinline__ void load_slice(const float4* __restrict__ src,
                                           int zc, int x, int r, int y0,
                                           float4& a, float4& b) {
    int zoff = (min(max(zc, 0), D - 1)) << 14;
    int ya = min(max(y0 + r - 2, 0), D - 1);
    a = src[x + (ya << 7) + zoff];
    if (r < 4) {
        int yb = min(max(y0 + r + 6, 0), D - 1);
        b = src[x + (yb << 7) + zoff];
    }
}

__global__ __launch_bounds__(1024) void conv3d_kernel(int sel, int first) {
    __shared__ float4 raw[12][D];
    __shared__ float4 xf[12][D];
    __shared__ unsigned s_mask;

    if (blockIdx.x == 0 && threadIdx.x == 0) {
        // fold convergence check: uses previous step's max displacement^2
        if (first) g_done = 0;
        else if (__uint_as_float(g_maxd2_bits) <= 1e-6f) g_done = 1;
        g_maxd2_bits = 0u;
    }

    const float4* __restrict__ src = sel ? g_gridB : g_gridA;
    const int* __restrict__ act = sel ? g_actB : g_actA;

    int x = threadIdx.x & 127;
    int r = threadIdx.x >> 7;            // 0..7
    int yt = blockIdx.x & 15;            // 16 y-tiles of 8 rows
    int z0 = (blockIdx.x >> 4) << 3;     // 16 z-segments of 8 slices
    int y0 = yt << 3;

    if (threadIdx.x < 32) {
        int f = (threadIdx.x < 8) ? act[(yt << 7) + z0 + threadIdx.x] : 0;
        unsigned bm = __ballot_sync(0xffffffffu, f != 0);
        if (threadIdx.x == 0) s_mask = bm;
    }
    __syncthreads();
    unsigned need = s_mask;
    if (!need) return;
    int zlo = z0 + __ffs(need) - 1;
    int zhi = z0 + 31 - __clz(need);
    int nslices = zhi - zlo + 5;         // raw slices zlo-2 .. zhi+2

    const float W0 = 1.f, W1 = 2.f, W2 = 3.f, W3 = 2.f, W4 = 1.f;

    float4 r0, r1, r2, r3, r4;           // z ring
    r0 = r1 = r2 = r3 = r4 = make_float4(0.f, 0.f, 0.f, 0.f);

    float4 pa, pb;                       // prefetch regs
    load_slice(src, zlo - 2, x, r, y0, pa, pb);

#pragma unroll 1
    for (int zi = 0; zi < nslices; zi++) {
        int zc = zlo - 2 + zi;
        raw[r][x] = pa;
        if (r < 4) raw[r + 8][x] = pb;
        __syncthreads();

        if (zi < nslices - 1) load_slice(src, zc + 1, x, r, y0, pa, pb);

        // x-filter
        {
            int xm2 = max(x - 2, 0), xm1 = max(x - 1, 0);
            int xp1 = min(x + 1, D - 1), xp2 = min(x + 2, D - 1);
            float4 a = make_float4(0.f, 0.f, 0.f, 0.f);
            fma4(a, W0, raw[r][xm2]); fma4(a, W1, raw[r][xm1]);
            fma4(a, W2, raw[r][x]);   fma4(a, W3, raw[r][xp1]);
            fma4(a, W4, raw[r][xp2]);
            xf[r][x] = a;
            if (r < 4) {
                float4 b = make_float4(0.f, 0.f, 0.f, 0.f);
                fma4(b, W0, raw[r + 8][xm2]); fma4(b, W1, raw[r + 8][xm1]);
                fma4(b, W2, raw[r + 8][x]);   fma4(b, W3, raw[r + 8][xp1]);
                fma4(b, W4, raw[r + 8][xp2]);
                xf[r + 8][x] = b;
            }
        }
        __syncthreads();

        // y-filter for core row (global y = y0 + r)
        float4 a = make_float4(0.f, 0.f, 0.f, 0.f);
        fma4(a, W0, xf[r + 0][x]);
        fma4(a, W1, xf[r + 1][x]);
        fma4(a, W2, xf[r + 2][x]);
        fma4(a, W3, xf[r + 3][x]);
        fma4(a, W4, xf[r + 4][x]);

        r0 = r1; r1 = r2; r2 = r3; r3 = r4; r4 = a;

        if (zi >= 4) {
            int zo = zc - 2;             // zlo .. zhi
            float4 o;
            o.x = r0.x + 2.f * r1.x + 3.f * r2.x + 2.f * r3.x + r4.x;
            o.y = r0.y + 2.f * r1.y + 3.f * r2.y + 2.f * r3.y + r4.y;
            o.z = r0.z + 2.f * r1.z + 3.f * r2.z + 2.f * r3.z + r4.z;
            o.w = r0.w + 2.f * r1.w + 3.f * r2.w + 2.f * r3.w + r4.w;
            g_grid1[x + ((y0 + r) << 7) + (zo << 14)] = o;
        }
        // no third sync: next raw store races only with xf reads (disjoint arrays)
    }
}

// ---------------------------------------------------------------- fused gather + scatter(next)
// Reads grid1[oldcell], computes newX, writes it, zeroes the consumed scatter
// grid + flags (restores all-zero invariant), scatters newX into the other
// grid for the next step, and accumulates max displacement^2.
__global__ void fused_gs_kernel(const float* __restrict__ Xext, int srcSel,
                                float* __restrict__ Oext, int dstSel,
                                int gsel, int doScatter, int n) {
    __shared__ float s_max[8];
    const float* X = (srcSel < 0) ? Xext : g_Xbuf[srcSel];
    float* Y = (dstSel < 0) ? Oext : g_Xbuf[dstSel];
    float4* gOld = gsel ? g_gridB : g_gridA;   // consumed this step -> zero
    float4* gNew = gsel ? g_gridA : g_gridB;   // next step's scatter target
    int* actOld = gsel ? g_actB : g_actA;
    int* actNew = gsel ? g_actA : g_actB;

    int i = blockIdx.x * blockDim.x + threadIdx.x;
    float d2 = 0.f;
    if (i < n) {
        float x = X[3 * i + 0];
        float y = X[3 * i + 1];
        float z = X[3 * i + 2];
        int yb = bin_of(y), zb = bin_of(z);
        int cell = bin_of(x) + (yb << 7) + (zb << 14);
        float4 t = g_grid1[cell];
        // undo this step's scatter: keeps grids & flags all-zero at boundaries
        gOld[cell] = make_float4(0.f, 0.f, 0.f, 0.f);
        actOld[((yb >> 3) << 7) + zb] = 0;
        float nx = __fdiv_rn(t.x, t.w);
        float ny = __fdiv_rn(t.y, t.w);
        float nz = __fdiv_rn(t.z, t.w);
        if (g_done) { nx = x; ny = y; nz = z; }
        Y[3 * i + 0] = nx;
        Y[3 * i + 1] = ny;
        Y[3 * i + 2] = nz;
        float dx = nx - x, dy = ny - y, dz = nz - z;
        d2 = dx * dx + dy * dy + dz * dz;
        if (doScatter) {
            int nyb = bin_of(ny), nzb = bin_of(nz);
            int ncell = bin_of(nx) + (nyb << 7) + (nzb << 14);
            actNew[((nyb >> 3) << 7) + nzb] = 1;
            red4(&gNew[ncell], nx, ny, nz, 1.0f);
        }
    }
#pragma unroll
    for (int o = 16; o > 0; o >>= 1)
        d2 = fmaxf(d2, __shfl_xor_sync(0xFFFFFFFFu, d2, o));
    int wid = threadIdx.x >> 5;
    if ((threadIdx.x & 31) == 0) s_max[wid] = d2;
    __syncthreads();
    if (threadIdx.x < 8) {
        float v = s_max[threadIdx.x];
#pragma unroll
        for (int o = 4; o > 0; o >>= 1)
            v = fmaxf(v, __shfl_xor_sync(0xFFu, v, o));
        if (threadIdx.x == 0)
            atomicMax(&g_maxd2_bits, __float_as_uint(v));
    }
}

// ---------------------------------------------------------------- launch
extern "C" void kernel_launch(void* const* d_in, const int* in_sizes, int n_in,
                              void* d_out, int out_size) {
    const float* Xin = (const float*)d_in[0];
    float* Out = (float*)d_out;
    int n = in_sizes[0] / 3;

    int pblocks = (n + 255) / 256;
    // step s: conv reads grid[gsel], fused_gs zeroes grid[gsel], scatters to grid[gsel^1]
    // gsel: 0,1,0,1,0  (A,B,A,B,A)
    int srcSel[5] = {-1, 0, 1, 0, 1};
    int dstSel[5] = { 0, 1, 0, 1, -1};

    scatter0_kernel<<<pblocks, 256>>>(Xin, n);
    for (int s = 0; s < 5; s++) {
        int gsel = s & 1;
        conv3d_kernel<<<256, 1024>>>(gsel, s == 0);
        fused_gs_kernel<<<pblocks, 256>>>(Xin, srcSel[s], Out, dstSel[s],
                                          gsel, s < 4, n);
    }
}